// round 11
// baseline (speedup 1.0000x reference)
#include <cuda_runtime.h>

#define EPS 1e-7f

constexpr int T  = 32;
constexpr int S  = 2048;
constexpr int NB = 512;               // batch
constexpr int SW = 8;                 // warps per block = s per block
constexpr int BTILE = 8;              // b per tile
constexpr int BGROUPS = 8;
constexpr int BPG = NB / BGROUPS;     // 64
constexpr int NSB = S / SW;           // 256
constexpr int BT  = NB * T;           // 16384
constexpr int NTILES = BPG / BTILE;   // 8

constexpr int BST  = 36;              // per-b float stride in xs
constexpr int XROW = BTILE * BST + 4; // 292 floats per s-row
constexpr int XS   = SW * XROW;       // 2336
constexpr int WST  = 36;              // per-warp(s) stride in op
constexpr int OPB  = SW * WST + 8;    // 296 per-b stride
constexpr int OPSZ = BTILE * OPB;     // 2368
// static smem: 2*(XS+OPSZ)*4 = 37632 B -> 2 blocks/SM

__device__ float g_partial[(size_t)NSB * BT];     // 16.8 MB deterministic scratch
__device__ float g_partial2[16 * BT];

__device__ __forceinline__ float tanh_approx(float x) {
    float y; asm("tanh.approx.f32 %0, %1;" : "=f"(y) : "f"(x)); return y;
}
__device__ __forceinline__ unsigned long long pack2(float lo, float hi) {
    unsigned long long r;
    asm("mov.b64 %0, {%1, %2};" : "=l"(r) : "f"(lo), "f"(hi));
    return r;
}
__device__ __forceinline__ void fma2(unsigned long long& d, unsigned long long a,
                                     unsigned long long b, unsigned long long c) {
    asm("fma.rn.f32x2 %0, %1, %2, %3;" : "=l"(d) : "l"(a), "l"(b), "l"(c));
}
__device__ __forceinline__ unsigned long long addf2(unsigned long long a,
                                                    unsigned long long b) {
    unsigned long long r;
    asm("add.rn.f32x2 %0, %1, %2;" : "=l"(r) : "l"(a), "l"(b));
    return r;
}
__device__ __forceinline__ void unpack2(float& lo, float& hi, unsigned long long a) {
    asm("mov.b64 {%0, %1}, %2;" : "=f"(lo), "=f"(hi) : "l"(a));
}

__global__ __launch_bounds__(256, 2) void attn_main(
    const float* __restrict__ inp, const float* __restrict__ msk,
    const float* __restrict__ W,   const float* __restrict__ bias)
{
    __shared__ float sm[2 * (XS + OPSZ)];
    float* xsb[2] = { sm, sm + XS };
    float* opb[2] = { sm + 2 * XS, sm + 2 * XS + OPSZ };

    const int tid  = threadIdx.x;
    const int w    = tid >> 5;          // warp = local s
    const int lane = tid & 31;
    const int ug   = lane & 3;          // u-octet: u = 8ug .. 8ug+7
    const int th   = lane >> 2;         // t-quad:  t = 4th .. 4th+3
    const int s0   = blockIdx.x * SW;
    const int bb   = blockIdx.y * BPG;
    const int s    = s0 + w;

    // W: lane holds W[4 t][8 u] = 32 floats = 16 f32x2 packed over u-pairs.
    unsigned long long w2[16];          // [k*4 + up]
    {
        const float* Wp = W + s * (T * T) + (4 * th) * 32 + 8 * ug;
        #pragma unroll
        for (int k = 0; k < 4; k++) {
            float4 a = *(const float4*)(Wp + k * 32);
            float4 b = *(const float4*)(Wp + k * 32 + 4);
            w2[k * 4 + 0] = pack2(a.x, a.y);
            w2[k * 4 + 1] = pack2(a.z, a.w);
            w2[k * 4 + 2] = pack2(b.x, b.y);
            w2[k * 4 + 3] = pack2(b.z, b.w);
        }
    }
    // final-ownership u-quad for this lane: u = uq .. uq+3
    const int uq = 8 * ug + 4 * (th >> 2);
    unsigned long long brg2[2];
    {
        float4 bv = *(const float4*)(bias + s * 32 + uq);
        brg2[0] = pack2(bv.x, bv.y);
        brg2[1] = pack2(bv.z, bv.w);
    }

    // staging: warp covers 16 t-rows x 32B = 512B per LDG.128
    const int sh = tid & 1;             // s-half (float4 of the 8 s)
    const int tt = (tid >> 1) & 31;     // t
    const int q  = tid >> 6;            // 0..3 -> b = q, q+4
    const float* ipb = inp + (size_t)bb * (T * S) + (size_t)tt * S + s0 + 4 * sh;
    const float* mpb = msk + (size_t)bb * (T * S) + (size_t)tt * S + s0 + 4 * sh;

    float4 px[2];
    #pragma unroll
    for (int j = 0; j < 2; j++) {
        size_t off = (size_t)(q + 4 * j) * (T * S);
        float4 iv = *(const float4*)(ipb + off);
        float4 mv = *(const float4*)(mpb + off);
        px[j] = make_float4(iv.x * mv.x, iv.y * mv.y, iv.z * mv.z, iv.w * mv.w);
    }

    const bool t0 = th & 1;
    const bool t1 = (th >> 1) & 1;
    const bool t2 = th >> 2;
    const int rb = tid >> 5, ru = tid & 31;   // reduce roles

    for (int bt = 0; bt < BPG; bt += BTILE) {
        const int ti  = bt / BTILE;
        const int cur = ti & 1;

        // ---- stage x -> xs[cur][4sh+i][b][tt]  (conflict-free STS) ----
        {
            float* xr = xsb[cur] + (4 * sh) * XROW + tt;
            #pragma unroll
            for (int j = 0; j < 2; j++) {
                float* p = xr + (q + 4 * j) * BST;
                p[0]        = px[j].x;
                p[XROW]     = px[j].y;
                p[2 * XROW] = px[j].z;
                p[3 * XROW] = px[j].w;
            }
        }

        // ---- prefetch next tile before the barrier ----
        if (bt + BTILE < BPG) {
            #pragma unroll
            for (int j = 0; j < 2; j++) {
                size_t off = (size_t)(bt + BTILE + q + 4 * j) * (T * S);
                float4 iv = *(const float4*)(ipb + off);
                float4 mv = *(const float4*)(mpb + off);
                px[j] = make_float4(iv.x * mv.x, iv.y * mv.y, iv.z * mv.z, iv.w * mv.w);
            }
        }
        __syncthreads();

        // ---- overlapped: reduce previous tile's op -> g_partial ----
        if (ti > 0) {
            const float* r = opb[cur ^ 1] + rb * OPB + ru;
            float sum = 0.f;
            #pragma unroll
            for (int k = 0; k < SW; k++) sum += r[k * WST];
            g_partial[(size_t)blockIdx.x * BT +
                      (size_t)(bb + bt - BTILE + rb) * T + ru] = sum;
        }

        // ---- compute: 2 groups of 4 b; lane does its 4t x 8u patch ----
        #pragma unroll
        for (int g = 0; g < 2; g++) {
            unsigned long long acc[16];
            #pragma unroll
            for (int i = 0; i < 16; i++) acc[i] = 0;

            #pragma unroll
            for (int bp = 0; bp < 4; bp++) {
                const float* xb = xsb[cur] + w * XROW + (4 * g + bp) * BST + 4 * th;
                float4 xv = *(const float4*)xb;     // x[4th..4th+3], this b
                unsigned long long d0 = pack2(xv.x, xv.x);
                unsigned long long d1 = pack2(xv.y, xv.y);
                unsigned long long d2 = pack2(xv.z, xv.z);
                unsigned long long d3 = pack2(xv.w, xv.w);
                #pragma unroll
                for (int up = 0; up < 4; up++) {
                    fma2(acc[bp * 4 + up], d0, w2[0 * 4 + up], acc[bp * 4 + up]);
                    fma2(acc[bp * 4 + up], d1, w2[1 * 4 + up], acc[bp * 4 + up]);
                    fma2(acc[bp * 4 + up], d2, w2[2 * 4 + up], acc[bp * 4 + up]);
                    fma2(acc[bp * 4 + up], d3, w2[3 * 4 + up], acc[bp * 4 + up]);
                }
            }

            // reduce-scatter over th: lane ends with b = 4g+(th&3), u = uq..uq+3
            unsigned long long c[8];
            #pragma unroll
            for (int up = 0; up < 4; up++) {
                unsigned long long lo = acc[0 * 4 + up], hi = acc[1 * 4 + up];
                unsigned long long snd = t0 ? lo : hi;
                unsigned long long rcv = __shfl_xor_sync(~0u, snd, 4);
                c[0 * 4 + up] = addf2(t0 ? hi : lo, rcv);
                lo = acc[2 * 4 + up]; hi = acc[3 * 4 + up];
                snd = t0 ? lo : hi;
                rcv = __shfl_xor_sync(~0u, snd, 4);
                c[1 * 4 + up] = addf2(t0 ? hi : lo, rcv);
            }
            unsigned long long z2[4];
            #pragma unroll
            for (int up = 0; up < 4; up++) {
                unsigned long long snd = t1 ? c[0 * 4 + up] : c[1 * 4 + up];
                unsigned long long rcv = __shfl_xor_sync(~0u, snd, 8);
                z2[up] = addf2(t1 ? c[1 * 4 + up] : c[0 * 4 + up], rcv);
            }
            unsigned long long zf[2];
            #pragma unroll
            for (int i = 0; i < 2; i++) {
                unsigned long long snd = t2 ? z2[i] : z2[2 + i];
                unsigned long long rcv = __shfl_xor_sync(~0u, snd, 16);
                zf[i] = addf2(t2 ? z2[2 + i] : z2[i], rcv);
            }
            zf[0] = addf2(zf[0], brg2[0]);
            zf[1] = addf2(zf[1], brg2[1]);

            float z0, z1, z2s, z3;
            unpack2(z0, z1, zf[0]);
            unpack2(z2s, z3, zf[1]);

            float e0 = __expf(tanh_approx(z0));
            float e1 = __expf(tanh_approx(z1));
            float e2 = __expf(tanh_approx(z2s));
            float e3 = __expf(tanh_approx(z3));

            // sum over u (lanes sharing b = same th&3: vary ug bits0-1, th bit2 = lane bit4)
            float r = (e0 + e1) + (e2 + e3);
            r += __shfl_xor_sync(~0u, r, 1);
            r += __shfl_xor_sync(~0u, r, 2);
            r += __shfl_xor_sync(~0u, r, 16);

            float inv = __fdividef(1.f, r + EPS);

            const int bf = 4 * g + (th & 3);
            const float* xwb = xsb[cur] + w * XROW + bf * BST + uq;   // x at t = u
            float4 xu = *(const float4*)xwb;

            float* od = opb[cur] + bf * OPB + w * WST + uq;
            *(float4*)od = make_float4(e0 * inv * xu.x, e1 * inv * xu.y,
                                       e2 * inv * xu.z, e3 * inv * xu.w);
        }
    }

    // ---- final tile's reduction ----
    __syncthreads();
    {
        const int lastcur = (NTILES - 1) & 1;
        const float* r = opb[lastcur] + rb * OPB + ru;
        float sum = 0.f;
        #pragma unroll
        for (int k = 0; k < SW; k++) sum += r[k * WST];
        g_partial[(size_t)blockIdx.x * BT +
                  (size_t)(bb + BPG - BTILE + rb) * T + ru] = sum;
    }
}

// stage A: 16 groups x 16 slices
__global__ void attn_reduceA()
{
    const int i = blockIdx.x * 256 + threadIdx.x;
    const int j = blockIdx.y;                    // 0..15
    const float* p = g_partial + (size_t)j * 16 * BT + i;
    float s = 0.f;
    #pragma unroll
    for (int k = 0; k < 16; k++) s += p[(size_t)k * BT];
    g_partial2[j * BT + i] = s;
}

__global__ void attn_reduceB(float* __restrict__ out)
{
    const int i = blockIdx.x * 256 + threadIdx.x;
    float s = 0.f;
    #pragma unroll
    for (int j = 0; j < 16; j++) s += g_partial2[j * BT + i];
    out[i] = s;
}

extern "C" void kernel_launch(void* const* d_in, const int* in_sizes, int n_in,
                              void* d_out, int out_size)
{
    const float* inp  = (const float*)d_in[0];
    const float* msk  = (const float*)d_in[1];
    const float* W    = (const float*)d_in[2];
    const float* bias = (const float*)d_in[3];
    float* out = (float*)d_out;

    dim3 grid(NSB, BGROUPS);
    attn_main<<<grid, 256>>>(inp, msk, W, bias);
    attn_reduceA<<<dim3(BT / 256, 16), 256>>>();
    attn_reduceB<<<BT / 256, 256>>>(out);
}